// round 15
// baseline (speedup 1.0000x reference)
#include <cuda_runtime.h>
#include <cuda_fp16.h>
#include <cstdint>

// ---------------------------------------------------------------------------
// Fused AUGRU cell, mma.sync FP16 m16n8k16 with FP16 accumulators promoted to
// FP32 every K=32 (tests the half-rate-fp32-acc hypothesis on the legacy pipe).
// Structure = R13 (best): fragment-permuted A+B, 256 thr, M=128 x N=32 CTA,
// 2 CTAs/SM, K64 chunks, 3-stage cp.async.
//   16 chunks: phase 0 (0-7) x@{Wu,Wr,Wh}, phase 1 (8-15) h@{Uu,Ur,Uh}.
// ---------------------------------------------------------------------------

#define TB 256

__device__ uint4 g_xa[1048576];   // x  fragment-permuted fp16 (16 MB)
__device__ uint4 g_ha[1048576];   // hidden, fragment-permuted fp16 (16 MB)
__device__ uint4 g_wb[196608];    // weights [ph][kc32][nb][w][ks][wn][lane] (3 MB)

#define A_BYTES    16384
#define B_BYTES    12288
#define BUF_BYTES  (A_BYTES + B_BYTES)   // 28672
#define SMEM_BYTES (3 * BUF_BYTES)       // 86016 (x2 CTAs <= 227K)

static __device__ __forceinline__ uint32_t smem_u32(const void* p) {
    uint32_t a;
    asm("{ .reg .u64 t; cvta.to.shared.u64 t, %1; cvt.u32.u64 %0, t; }"
        : "=r"(a) : "l"(p));
    return a;
}
static __device__ __forceinline__ void cp16(uint32_t dst, const void* src) {
    asm volatile("cp.async.cg.shared.global [%0], [%1], 16;"
                 :: "r"(dst), "l"(src) : "memory");
}
static __device__ __forceinline__ void cp_commit() {
    asm volatile("cp.async.commit_group;" ::: "memory");
}
static __device__ __forceinline__ uint32_t pack2(float lo, float hi) {
    uint32_t r;
    asm("cvt.rn.f16x2.f32 %0, %2, %1;" : "=r"(r) : "f"(lo), "f"(hi));
    return r;
}
// f16-accumulator mma: D,C are 2x f16x2 regs.
static __device__ __forceinline__ void mma16h(uint32_t* d, const uint4& a,
                                              uint32_t b0, uint32_t b1) {
    asm volatile(
        "mma.sync.aligned.m16n8k16.row.col.f16.f16.f16.f16 "
        "{%0,%1}, {%2,%3,%4,%5}, {%6,%7}, {%0,%1};"
        : "+r"(d[0]), "+r"(d[1])
        : "r"(a.x), "r"(a.y), "r"(a.z), "r"(a.w), "r"(b0), "r"(b1));
}
static __device__ __forceinline__ void promote(float* acc, const uint32_t* p) {
    const __half2 h0 = *reinterpret_cast<const __half2*>(&p[0]);
    const __half2 h1 = *reinterpret_cast<const __half2*>(&p[1]);
    acc[0] += __low2float(h0);
    acc[1] += __high2float(h0);
    acc[2] += __low2float(h1);
    acc[3] += __high2float(h1);
}
static __device__ __forceinline__ float sigmoidf_fast(float z) {
    return 1.0f / (1.0f + __expf(-z));
}
static __device__ __forceinline__ float tanhf_fast(float z) {
    return 1.0f - 2.0f / (1.0f + __expf(2.0f * z));
}

// ---- pre-pass A: staged transpose, coalesced both sides --------------------
__global__ void __launch_bounds__(256)
permA_kernel(const float* __restrict__ x, const float* __restrict__ hid)
{
    __shared__ uint32_t st[256 * 17];
    const int mB = blockIdx.x;
    const float* src = blockIdx.y ? hid : x;
    uint4*       dst = blockIdx.y ? g_ha : g_xa;
    const float4* s4 = reinterpret_cast<const float4*>(src + (size_t)mB * 16 * 512);

    #pragma unroll
    for (int it = 0; it < 8; it++) {
        const int idx = threadIdx.x + 256 * it;
        const int r   = idx >> 7;
        const int c4  = idx & 127;
        const float4 v = __ldg(s4 + r * 128 + c4);
        const int c = c4 * 2;
        st[c * 17 + r]       = pack2(v.x, v.y);
        st[(c + 1) * 17 + r] = pack2(v.z, v.w);
    }
    __syncthreads();

    #pragma unroll
    for (int it = 0; it < 4; it++) {
        const int idx  = threadIdx.x + 256 * it;
        const int lane = idx & 31;
        const int ks   = (idx >> 5) & 1;
        const int kc   = idx >> 6;
        const int g = lane >> 2, t = lane & 3;
        const int c = kc * 16 + ks * 8 + t;
        uint4 o;
        o.x = st[c * 17 + g];
        o.y = st[c * 17 + g + 8];
        o.z = st[(c + 4) * 17 + g];
        o.w = st[(c + 4) * 17 + g + 8];
        dst[(size_t)mB * 1024 + idx] = o;
    }
}

// ---- pre-pass B -------------------------------------------------------------
__global__ void __launch_bounds__(256)
permB_kernel(const float* __restrict__ Wu, const float* __restrict__ Wr,
             const float* __restrict__ Wh, const float* __restrict__ Uu,
             const float* __restrict__ Ur, const float* __restrict__ Uh)
{
    const int gi = blockIdx.x * 256 + threadIdx.x;
    const int w  = blockIdx.y;
    const int ph = w / 3, w3 = w % 3;
    const float* ws[6] = {Wu, Wr, Wh, Uu, Ur, Uh};
    const float* src = ws[w];
    const int kc   = gi >> 11;
    const int rem  = gi & 2047;
    const int nb   = rem >> 8;
    const int rem2 = rem & 255;
    const int ks   = rem2 >> 7;
    const int wn   = (rem2 >> 5) & 3;
    const int lane = rem2 & 31;
    const int g = lane >> 2, t = lane & 3;
    const int k = kc * 32 + ks * 16 + 2 * t;
    const int n = nb * 64 + wn * 16 + g;
    const float* pk = src + (size_t)k * 512 + n;
    uint4 o;
    o.x = pack2(__ldg(pk),               __ldg(pk + 512));
    o.y = pack2(__ldg(pk + 8 * 512),     __ldg(pk + 9 * 512));
    o.z = pack2(__ldg(pk + 8),           __ldg(pk + 512 + 8));
    o.w = pack2(__ldg(pk + 8 * 512 + 8), __ldg(pk + 9 * 512 + 8));
    const size_t di = ((size_t)((((ph * 16 + kc) * 8 + nb) * 3 + w3) * 2 + ks)) * 128
                    + wn * 32 + lane;
    g_wb[di] = o;
}

// ---- main fused kernel: 2 CTAs/SM, fp16 psums + fp32 master acc ------------
__global__ void __launch_bounds__(TB, 2)
augru_kernel(const float* __restrict__ att, const float* __restrict__ hid,
             const float* __restrict__ b_u, const float* __restrict__ b_r,
             const float* __restrict__ b_h, float* __restrict__ out)
{
    extern __shared__ char smc[];
    const uint32_t sb = smem_u32(smc);
    const int tid  = threadIdx.x;
    const int lane = tid & 31;
    const int wid  = tid >> 5;
    const int g = lane >> 2;
    const int t = lane & 3;
    const int wm  = wid & 3;
    const int wn2 = wid >> 2;
    const int m0 = (int)blockIdx.y << 7;
    const int n0 = (int)blockIdx.x << 5;
    const int mB0   = m0 >> 4;
    const int nb    = (int)blockIdx.x >> 1;
    const int halfn = (int)blockIdx.x & 1;

    float accU[2][2][4], accR[2][2][4], accX[2][2][4], accS[2][2][4];
    #pragma unroll
    for (int mt = 0; mt < 2; mt++)
        #pragma unroll
        for (int nt = 0; nt < 2; nt++)
            #pragma unroll
            for (int e = 0; e < 4; e++) {
                accU[mt][nt][e] = 0.f; accR[mt][nt][e] = 0.f;
                accX[mt][nt][e] = 0.f; accS[mt][nt][e] = 0.f;
            }

    auto load_chunk = [&](int c, int b) {
        const int ph = (c >= 8);
        const int cc = c & 7;
        const uint32_t bo = sb + (uint32_t)b * BUF_BYTES;
        const uint4* Ag = ph ? g_ha : g_xa;
        #pragma unroll
        for (int i = 0; i < 4; i++) {
            const int j   = tid + TB * i;
            const int mb  = j >> 7;
            const int low = j & 127;
            cp16(bo + j * 16,
                 Ag + ((size_t)(mB0 + mb) * 1024 + cc * 128 + low));
        }
        const uint4* Bsrc = g_wb + ((size_t)((ph * 16 + 2 * cc) * 8 + nb)) * 768
                          + halfn * 64;
        #pragma unroll
        for (int i = 0; i < 3; i++) {
            const int j   = tid + TB * i;
            const int kh  = j / 384;
            const int r2  = j - kh * 384;
            const int sub = r2 >> 6;
            const int low = r2 & 63;
            cp16(bo + B_BYTES + 0 + j * 16 - B_BYTES +
                     A_BYTES, Bsrc + (size_t)kh * 6144 + sub * 128 + low);
        }
        cp_commit();
    };

    load_chunk(0, 0);
    load_chunk(1, 1);

    for (int c = 0; c < 16; c++) {
        const int b = c % 3;
        if (c == 15) asm volatile("cp.async.wait_group 0;" ::: "memory");
        else         asm volatile("cp.async.wait_group 1;" ::: "memory");
        __syncthreads();
        if (c + 2 < 16) load_chunk(c + 2, (c + 2) % 3);

        const uint4* Ab4 = reinterpret_cast<const uint4*>(smc + b * BUF_BYTES);
        const uint4* Bb4 = reinterpret_cast<const uint4*>(smc + b * BUF_BYTES + A_BYTES);
        const int ph = (c >= 8);

        #pragma unroll
        for (int khalf = 0; khalf < 2; khalf++) {
            // fp16 psums for this K=32 window
            uint32_t pU[2][2][2], pR[2][2][2], pC[2][2][2];
            #pragma unroll
            for (int mt = 0; mt < 2; mt++)
                #pragma unroll
                for (int nt = 0; nt < 2; nt++) {
                    pU[mt][nt][0] = 0u; pU[mt][nt][1] = 0u;
                    pR[mt][nt][0] = 0u; pR[mt][nt][1] = 0u;
                    pC[mt][nt][0] = 0u; pC[mt][nt][1] = 0u;
                }
            #pragma unroll
            for (int ks2 = 0; ks2 < 2; ks2++) {
                uint4 a[2];
                #pragma unroll
                for (int mt = 0; mt < 2; mt++) {
                    const int mb = wm * 2 + mt;
                    a[mt] = Ab4[mb * 128 + khalf * 64 + ks2 * 32 + lane];
                }
                uint4 bv[3];
                #pragma unroll
                for (int w = 0; w < 3; w++)
                    bv[w] = Bb4[khalf * 384 + (w * 2 + ks2) * 64 + wn2 * 32 + lane];
                #pragma unroll
                for (int mt = 0; mt < 2; mt++) {
                    mma16h(pU[mt][0], a[mt], bv[0].x, bv[0].y);
                    mma16h(pU[mt][1], a[mt], bv[0].z, bv[0].w);
                    mma16h(pR[mt][0], a[mt], bv[1].x, bv[1].y);
                    mma16h(pR[mt][1], a[mt], bv[1].z, bv[1].w);
                    mma16h(pC[mt][0], a[mt], bv[2].x, bv[2].y);
                    mma16h(pC[mt][1], a[mt], bv[2].z, bv[2].w);
                }
            }
            // promote window psums into fp32 master accumulators
            #pragma unroll
            for (int mt = 0; mt < 2; mt++)
                #pragma unroll
                for (int nt = 0; nt < 2; nt++) {
                    promote(accU[mt][nt], pU[mt][nt]);
                    promote(accR[mt][nt], pR[mt][nt]);
                    if (!ph) promote(accX[mt][nt], pC[mt][nt]);
                    else     promote(accS[mt][nt], pC[mt][nt]);
                }
        }
    }

    // ---- epilogue ----------------------------------------------------------
    #pragma unroll
    for (int mt = 0; mt < 2; mt++) {
        #pragma unroll
        for (int er = 0; er < 2; er++) {
            const int m = m0 + wm * 32 + mt * 16 + g + er * 8;
            const float am = __ldg(att + m);
            const float* hrow = hid + (size_t)m * 512;
            float*       orow = out + (size_t)m * 512;
            #pragma unroll
            for (int nt = 0; nt < 2; nt++) {
                const int col = n0 + wn2 * 16 + nt * 8 + t * 2;
                const float2 h2  = __ldg((const float2*)(hrow + col));
                const float2 bu2 = __ldg((const float2*)(b_u + col));
                const float2 br2 = __ldg((const float2*)(b_r + col));
                const float2 bh2 = __ldg((const float2*)(b_h + col));
                float o[2];
                #pragma unroll
                for (int ec = 0; ec < 2; ec++) {
                    const int e = er * 2 + ec;
                    const float zu = accU[mt][nt][e] + (ec ? bu2.y : bu2.x);
                    const float zr = accR[mt][nt][e] + (ec ? br2.y : br2.x);
                    const float u  = am * sigmoidf_fast(zu);
                    const float r  = sigmoidf_fast(zr);
                    const float hh = tanhf_fast(accX[mt][nt][e] +
                                                r * accS[mt][nt][e] +
                                                (ec ? bh2.y : bh2.x));
                    const float hv = ec ? h2.y : h2.x;
                    o[ec] = (1.0f - u) * hv + u * hh;
                }
                *(float2*)(orow + col) = make_float2(o[0], o[1]);
            }
        }
    }
}

extern "C" void kernel_launch(void* const* d_in, const int* in_sizes, int n_in,
                              void* d_out, int out_size) {
    (void)in_sizes; (void)n_in; (void)out_size;
    const float* x   = (const float*)d_in[0];
    const float* att = (const float*)d_in[1];
    const float* hid = (const float*)d_in[2];
    const float* Wu  = (const float*)d_in[3];
    const float* Uu  = (const float*)d_in[4];
    const float* b_u = (const float*)d_in[5];
    const float* Wr  = (const float*)d_in[6];
    const float* Ur  = (const float*)d_in[7];
    const float* b_r = (const float*)d_in[8];
    const float* Wh  = (const float*)d_in[9];
    const float* Uh  = (const float*)d_in[10];
    const float* b_h = (const float*)d_in[11];
    float* out = (float*)d_out;

    permA_kernel<<<dim3(1024, 2), 256>>>(x, hid);
    permB_kernel<<<dim3(128, 6), 256>>>(Wu, Wr, Wh, Uu, Ur, Uh);

    cudaFuncSetAttribute(augru_kernel,
                         cudaFuncAttributeMaxDynamicSharedMemorySize, SMEM_BYTES);
    dim3 grid(16, 128, 1);
    augru_kernel<<<grid, TB, SMEM_BYTES>>>(att, hid, b_u, b_r, b_h, out);
}

// round 16
// speedup vs baseline: 1.1179x; 1.1179x over previous
#include <cuda_runtime.h>
#include <cuda_fp16.h>
#include <cstdint>

// ---------------------------------------------------------------------------
// Fused AUGRU cell, mma.sync FP16 m16n8k16 (sm_100-target-safe PTX).
// Round 16 = R13 (best, 212.3us) + chunk-order rotation keyed on CTA parity:
// co-resident CTAs visit chunks half-a-phase out of step so their
// cp.async-wait + __syncthreads convoys interleave instead of colliding.
//   256 thr, M=128 x N=32 CTA, 2 CTAs/SM, K64 chunks, 3-stage cp.async.
//   16 chunks: phase 0 (0-7) x@{Wu,Wr,Wh}, phase 1 (8-15) h@{Uu,Ur,Uh}.
// A group (16B, 8 fp16) = m16n8k16 A-fragment (see permA).
// B group (16B) = B-fragments for two n8 tiles (see permB).
// ---------------------------------------------------------------------------

#define TB 256

__device__ uint4 g_xa[1048576];   // x  fragment-permuted fp16 (16 MB)
__device__ uint4 g_ha[1048576];   // hidden, fragment-permuted fp16 (16 MB)
__device__ uint4 g_wb[196608];    // weights [ph][kc32][nb][w][ks][wn][lane] (3 MB)

#define A_BYTES    16384
#define B_BYTES    12288
#define BUF_BYTES  (A_BYTES + B_BYTES)   // 28672
#define SMEM_BYTES (3 * BUF_BYTES)       // 86016 (x2 CTAs <= 227K)

static __device__ __forceinline__ uint32_t smem_u32(const void* p) {
    uint32_t a;
    asm("{ .reg .u64 t; cvta.to.shared.u64 t, %1; cvt.u32.u64 %0, t; }"
        : "=r"(a) : "l"(p));
    return a;
}
static __device__ __forceinline__ void cp16(uint32_t dst, const void* src) {
    asm volatile("cp.async.cg.shared.global [%0], [%1], 16;"
                 :: "r"(dst), "l"(src) : "memory");
}
static __device__ __forceinline__ void cp_commit() {
    asm volatile("cp.async.commit_group;" ::: "memory");
}
static __device__ __forceinline__ uint32_t pack2(float lo, float hi) {
    uint32_t r;
    asm("cvt.rn.f16x2.f32 %0, %2, %1;" : "=r"(r) : "f"(lo), "f"(hi));
    return r;
}
static __device__ __forceinline__ void mma16(float* d, const uint4& a,
                                             uint32_t b0, uint32_t b1) {
    asm volatile(
        "mma.sync.aligned.m16n8k16.row.col.f32.f16.f16.f32 "
        "{%0,%1,%2,%3}, {%4,%5,%6,%7}, {%8,%9}, {%0,%1,%2,%3};"
        : "+f"(d[0]), "+f"(d[1]), "+f"(d[2]), "+f"(d[3])
        : "r"(a.x), "r"(a.y), "r"(a.z), "r"(a.w), "r"(b0), "r"(b1));
}
static __device__ __forceinline__ float sigmoidf_fast(float z) {
    return 1.0f / (1.0f + __expf(-z));
}
static __device__ __forceinline__ float tanhf_fast(float z) {
    return 1.0f - 2.0f / (1.0f + __expf(2.0f * z));
}

// ---- pre-pass A: staged transpose, coalesced both sides --------------------
// grid (1024, 2) x 256. Block = 16 rows x 512 cols.
__global__ void __launch_bounds__(256)
permA_kernel(const float* __restrict__ x, const float* __restrict__ hid)
{
    __shared__ uint32_t st[256 * 17];
    const int mB = blockIdx.x;
    const float* src = blockIdx.y ? hid : x;
    uint4*       dst = blockIdx.y ? g_ha : g_xa;
    const float4* s4 = reinterpret_cast<const float4*>(src + (size_t)mB * 16 * 512);

    #pragma unroll
    for (int it = 0; it < 8; it++) {
        const int idx = threadIdx.x + 256 * it;
        const int r   = idx >> 7;
        const int c4  = idx & 127;
        const float4 v = __ldg(s4 + r * 128 + c4);
        const int c = c4 * 2;
        st[c * 17 + r]       = pack2(v.x, v.y);
        st[(c + 1) * 17 + r] = pack2(v.z, v.w);
    }
    __syncthreads();

    #pragma unroll
    for (int it = 0; it < 4; it++) {
        const int idx  = threadIdx.x + 256 * it;
        const int lane = idx & 31;
        const int ks   = (idx >> 5) & 1;
        const int kc   = idx >> 6;
        const int g = lane >> 2, t = lane & 3;
        const int c = kc * 16 + ks * 8 + t;
        uint4 o;
        o.x = st[c * 17 + g];
        o.y = st[c * 17 + g + 8];
        o.z = st[(c + 4) * 17 + g];
        o.w = st[(c + 4) * 17 + g + 8];
        dst[(size_t)mB * 1024 + idx] = o;
    }
}

// ---- pre-pass B: grid (128, 6) x 256 ---------------------------------------
__global__ void __launch_bounds__(256)
permB_kernel(const float* __restrict__ Wu, const float* __restrict__ Wr,
             const float* __restrict__ Wh, const float* __restrict__ Uu,
             const float* __restrict__ Ur, const float* __restrict__ Uh)
{
    const int gi = blockIdx.x * 256 + threadIdx.x;
    const int w  = blockIdx.y;
    const int ph = w / 3, w3 = w % 3;
    const float* ws[6] = {Wu, Wr, Wh, Uu, Ur, Uh};
    const float* src = ws[w];
    const int kc   = gi >> 11;
    const int rem  = gi & 2047;
    const int nb   = rem >> 8;
    const int rem2 = rem & 255;
    const int ks   = rem2 >> 7;
    const int wn   = (rem2 >> 5) & 3;
    const int lane = rem2 & 31;
    const int g = lane >> 2, t = lane & 3;
    const int k = kc * 32 + ks * 16 + 2 * t;
    const int n = nb * 64 + wn * 16 + g;
    const float* pk = src + (size_t)k * 512 + n;
    uint4 o;
    o.x = pack2(__ldg(pk),               __ldg(pk + 512));
    o.y = pack2(__ldg(pk + 8 * 512),     __ldg(pk + 9 * 512));
    o.z = pack2(__ldg(pk + 8),           __ldg(pk + 512 + 8));
    o.w = pack2(__ldg(pk + 8 * 512 + 8), __ldg(pk + 9 * 512 + 8));
    const size_t di = ((size_t)((((ph * 16 + kc) * 8 + nb) * 3 + w3) * 2 + ks)) * 128
                    + wn * 32 + lane;
    g_wb[di] = o;
}

// ---- main fused kernel: 2 CTAs/SM, parity-rotated chunk order --------------
__global__ void __launch_bounds__(TB, 2)
augru_kernel(const float* __restrict__ att, const float* __restrict__ hid,
             const float* __restrict__ b_u, const float* __restrict__ b_r,
             const float* __restrict__ b_h, float* __restrict__ out)
{
    extern __shared__ char smc[];
    const uint32_t sb = smem_u32(smc);
    const int tid  = threadIdx.x;
    const int lane = tid & 31;
    const int wid  = tid >> 5;
    const int g = lane >> 2;
    const int t = lane & 3;
    const int wm  = wid & 3;       // 4 warp-rows of 32
    const int wn2 = wid >> 2;      // 2 warp-cols of 16
    const int m0 = (int)blockIdx.y << 7;
    const int n0 = (int)blockIdx.x << 5;      // 32-col tile
    const int mB0   = m0 >> 4;
    const int nb    = (int)blockIdx.x >> 1;   // 64-col block in permB layout
    const int halfn = (int)blockIdx.x & 1;
    // Dephase co-resident CTAs: rotate chunk order within each phase.
    const int rot = (blockIdx.y & 1) ? 4 : 0;

    float accU[2][2][4], accR[2][2][4], accX[2][2][4], accS[2][2][4];
    #pragma unroll
    for (int mt = 0; mt < 2; mt++)
        #pragma unroll
        for (int nt = 0; nt < 2; nt++)
            #pragma unroll
            for (int e = 0; e < 4; e++) {
                accU[mt][nt][e] = 0.f; accR[mt][nt][e] = 0.f;
                accX[mt][nt][e] = 0.f; accS[mt][nt][e] = 0.f;
            }

    // chunk = 64 K-columns. 16 chunks (8 per phase), visited rotated by rot.
    auto load_chunk = [&](int c, int b) {
        const int ph = (c >= 8);
        const int cc = ((c & 7) + rot) & 7;
        const uint32_t bo = sb + (uint32_t)b * BUF_BYTES;
        // A: 1024 groups, 4 per thread.
        const uint4* Ag = ph ? g_ha : g_xa;
        #pragma unroll
        for (int i = 0; i < 4; i++) {
            const int j   = tid + TB * i;      // 0..1023
            const int mb  = j >> 7;
            const int low = j & 127;
            cp16(bo + j * 16,
                 Ag + ((size_t)(mB0 + mb) * 1024 + cc * 128 + low));
        }
        // B: 768 groups = 2 kc32-blocks x 6 (w,ks) x 64 (our half), 3/thread.
        const uint4* Bsrc = g_wb + ((size_t)((ph * 16 + 2 * cc) * 8 + nb)) * 768
                          + halfn * 64;
        #pragma unroll
        for (int i = 0; i < 3; i++) {
            const int j   = tid + TB * i;      // 0..767
            const int kh  = j / 384;
            const int r2  = j - kh * 384;
            const int sub = r2 >> 6;           // (w,ks) 0..5
            const int low = r2 & 63;
            cp16(bo + A_BYTES + j * 16,
                 Bsrc + (size_t)kh * 6144 + sub * 128 + low);
        }
        cp_commit();
    };

    load_chunk(0, 0);
    load_chunk(1, 1);

    for (int c = 0; c < 16; c++) {
        const int b = c % 3;
        if (c == 15) asm volatile("cp.async.wait_group 0;" ::: "memory");
        else         asm volatile("cp.async.wait_group 1;" ::: "memory");
        __syncthreads();
        if (c + 2 < 16) load_chunk(c + 2, (c + 2) % 3);

        const uint4* Ab4 = reinterpret_cast<const uint4*>(smc + b * BUF_BYTES);
        const uint4* Bb4 = reinterpret_cast<const uint4*>(smc + b * BUF_BYTES + A_BYTES);
        const int ph = (c >= 8);

        #pragma unroll
        for (int ks = 0; ks < 4; ks++) {
            const int khalf = ks >> 1, ks2 = ks & 1;
            uint4 a[2];
            #pragma unroll
            for (int mt = 0; mt < 2; mt++) {
                const int mb = wm * 2 + mt;
                a[mt] = Ab4[mb * 128 + khalf * 64 + ks2 * 32 + lane];
            }
            uint4 bv[3];
            #pragma unroll
            for (int w = 0; w < 3; w++)
                bv[w] = Bb4[khalf * 384 + (w * 2 + ks2) * 64 + wn2 * 32 + lane];
            #pragma unroll
            for (int mt = 0; mt < 2; mt++) {
                mma16(accU[mt][0], a[mt], bv[0].x, bv[0].y);
                mma16(accU[mt][1], a[mt], bv[0].z, bv[0].w);
                mma16(accR[mt][0], a[mt], bv[1].x, bv[1].y);
                mma16(accR[mt][1], a[mt], bv[1].z, bv[1].w);
                if (!ph) {
                    mma16(accX[mt][0], a[mt], bv[2].x, bv[2].y);
                    mma16(accX[mt][1], a[mt], bv[2].z, bv[2].w);
                } else {
                    mma16(accS[mt][0], a[mt], bv[2].x, bv[2].y);
                    mma16(accS[mt][1], a[mt], bv[2].z, bv[2].w);
                }
            }
        }
    }

    // ---- epilogue ----------------------------------------------------------
    #pragma unroll
    for (int mt = 0; mt < 2; mt++) {
        #pragma unroll
        for (int er = 0; er < 2; er++) {
            const int m = m0 + wm * 32 + mt * 16 + g + er * 8;
            const float am = __ldg(att + m);
            const float* hrow = hid + (size_t)m * 512;
            float*       orow = out + (size_t)m * 512;
            #pragma unroll
            for (int nt = 0; nt < 2; nt++) {
                const int col = n0 + wn2 * 16 + nt * 8 + t * 2;
                const float2 h2  = __ldg((const float2*)(hrow + col));
                const float2 bu2 = __ldg((const float2*)(b_u + col));
                const float2 br2 = __ldg((const float2*)(b_r + col));
                const float2 bh2 = __ldg((const float2*)(b_h + col));
                float o[2];
                #pragma unroll
                for (int ec = 0; ec < 2; ec++) {
                    const int e = er * 2 + ec;
                    const float zu = accU[mt][nt][e] + (ec ? bu2.y : bu2.x);
                    const float zr = accR[mt][nt][e] + (ec ? br2.y : br2.x);
                    const float u  = am * sigmoidf_fast(zu);
                    const float r  = sigmoidf_fast(zr);
                    const float hh = tanhf_fast(accX[mt][nt][e] +
                                                r * accS[mt][nt][e] +
                                                (ec ? bh2.y : bh2.x));
                    const float hv = ec ? h2.y : h2.x;
                    o[ec] = (1.0f - u) * hv + u * hh;
                }
                *(float2*)(orow + col) = make_float2(o[0], o[1]);
            }
        }
    }
}

extern "C" void kernel_launch(void* const* d_in, const int* in_sizes, int n_in,
                              void* d_out, int out_size) {
    (void)in_sizes; (void)n_in; (void)out_size;
    const float* x   = (const float*)d_in[0];
    const float* att = (const float*)d_in[1];
    const float* hid = (const float*)d_in[2];
    const float* Wu  = (const float*)d_in[3];
    const float* Uu  = (const float*)d_in[4];
    const float* b_u = (const float*)d_in[5];
    const float* Wr  = (const float*)d_in[6];
    const float* Ur  = (const float*)d_in[7];
    const float* b_r = (const float*)d_in[8];
    const float* Wh  = (const float*)d_in[9];
    const float* Uh  = (const float*)d_in[10];
    const float* b_h = (const float*)d_in[11];
    float* out = (float*)d_out;

    permA_kernel<<<dim3(1024, 2), 256>>>(x, hid);
    permB_kernel<<<dim3(128, 6), 256>>>(Wu, Wr, Wh, Uu, Ur, Uh);

    cudaFuncSetAttribute(augru_kernel,
                         cudaFuncAttributeMaxDynamicSharedMemorySize, SMEM_BYTES);
    dim3 grid(16, 128, 1);   // 16 N-tiles x 128 M-tiles
    augru_kernel<<<grid, TB, SMEM_BYTES>>>(att, hid, b_u, b_r, b_h, out);
}

// round 17
// speedup vs baseline: 1.1587x; 1.0365x over previous
#include <cuda_runtime.h>
#include <cuda_fp16.h>
#include <cstdint>

// ---------------------------------------------------------------------------
// Fused AUGRU cell, mma.sync FP16 m16n8k16 (sm_100-target-safe PTX).
// Round 17 = R13 mainloop (best) + merged/conflict-free prepass:
//   - permA phase-1 staging now STS conflict-free (float2 per thread).
//   - permA and permB fused into ONE kernel launch (permB blocks fill idle SMs).
//   256 thr, M=128 x N=32 CTA, 2 CTAs/SM, K64 chunks, 3-stage cp.async.
//   16 chunks: phase 0 (0-7) x@{Wu,Wr,Wh}, phase 1 (8-15) h@{Uu,Ur,Uh}.
// A group (16B, 8 fp16) = m16n8k16 A-fragment of thread (g,t):
//   { A[r][k],A[r][k+1] | A[r+8][k],A[r+8][k+1] |
//     A[r][k+8],A[r][k+9] | A[r+8][k+8],A[r+8][k+9] },  r=mB*16+g, k=base+2t.
// B group (16B) = B-fragments for two n8 tiles.
// ---------------------------------------------------------------------------

#define TB 256

__device__ uint4 g_xa[1048576];   // x  fragment-permuted fp16 (16 MB)
__device__ uint4 g_ha[1048576];   // hidden, fragment-permuted fp16 (16 MB)
__device__ uint4 g_wb[196608];    // weights [ph][kc32][nb][w][ks][wn][lane] (3 MB)

#define A_BYTES    16384
#define B_BYTES    12288
#define BUF_BYTES  (A_BYTES + B_BYTES)   // 28672
#define SMEM_BYTES (3 * BUF_BYTES)       // 86016 (x2 CTAs <= 227K)

static __device__ __forceinline__ uint32_t smem_u32(const void* p) {
    uint32_t a;
    asm("{ .reg .u64 t; cvta.to.shared.u64 t, %1; cvt.u32.u64 %0, t; }"
        : "=r"(a) : "l"(p));
    return a;
}
static __device__ __forceinline__ void cp16(uint32_t dst, const void* src) {
    asm volatile("cp.async.cg.shared.global [%0], [%1], 16;"
                 :: "r"(dst), "l"(src) : "memory");
}
static __device__ __forceinline__ void cp_commit() {
    asm volatile("cp.async.commit_group;" ::: "memory");
}
static __device__ __forceinline__ uint32_t pack2(float lo, float hi) {
    uint32_t r;
    asm("cvt.rn.f16x2.f32 %0, %2, %1;" : "=r"(r) : "f"(lo), "f"(hi));
    return r;
}
static __device__ __forceinline__ void mma16(float* d, const uint4& a,
                                             uint32_t b0, uint32_t b1) {
    asm volatile(
        "mma.sync.aligned.m16n8k16.row.col.f32.f16.f16.f32 "
        "{%0,%1,%2,%3}, {%4,%5,%6,%7}, {%8,%9}, {%0,%1,%2,%3};"
        : "+f"(d[0]), "+f"(d[1]), "+f"(d[2]), "+f"(d[3])
        : "r"(a.x), "r"(a.y), "r"(a.z), "r"(a.w), "r"(b0), "r"(b1));
}
static __device__ __forceinline__ float sigmoidf_fast(float z) {
    return 1.0f / (1.0f + __expf(-z));
}
static __device__ __forceinline__ float tanhf_fast(float z) {
    return 1.0f - 2.0f / (1.0f + __expf(2.0f * z));
}

// ---- merged pre-pass --------------------------------------------------------
// grid 2816 x 256:
//   blocks [0, 2048):    permA  (matrix = bx&1, mB = bx>>1)
//   blocks [2048, 2816): permB  (w = idx/128, sub-block = idx%128)
__global__ void __launch_bounds__(256)
perm_kernel(const float* __restrict__ x,  const float* __restrict__ hid,
            const float* __restrict__ Wu, const float* __restrict__ Wr,
            const float* __restrict__ Wh, const float* __restrict__ Uu,
            const float* __restrict__ Ur, const float* __restrict__ Uh)
{
    const int bx = blockIdx.x;
    if (bx < 2048) {
        // ---- permA: block = 16 rows x 512 cols, staged transpose ----------
        __shared__ uint32_t st[256 * 17];
        const int mB = bx >> 1;
        const float* src = (bx & 1) ? hid : x;
        uint4*       dst = (bx & 1) ? g_ha : g_xa;
        const float2* s2 = reinterpret_cast<const float2*>(src + (size_t)mB * 16 * 512);

        // phase 1: one float2 per thread per iter; STS addr = 17c + r with
        // c = lane + const -> all 32 banks distinct (conflict-free).
        #pragma unroll
        for (int it = 0; it < 16; it++) {
            const int idx = threadIdx.x + 256 * it;   // 0..4095
            const int r   = idx >> 8;                  // row 0..15
            const int c   = idx & 255;                 // fp16-pair col
            const float2 v = __ldg(s2 + r * 256 + c);
            st[c * 17 + r] = pack2(v.x, v.y);
        }
        __syncthreads();

        // phase 2: gather fragment groups, coalesced uint4 store
        #pragma unroll
        for (int it = 0; it < 4; it++) {
            const int idx  = threadIdx.x + 256 * it;  // 0..1023
            const int lane = idx & 31;
            const int ks   = (idx >> 5) & 1;
            const int kc   = idx >> 6;
            const int g = lane >> 2, t = lane & 3;
            const int c = kc * 16 + ks * 8 + t;
            uint4 o;
            o.x = st[c * 17 + g];
            o.y = st[c * 17 + g + 8];
            o.z = st[(c + 4) * 17 + g];
            o.w = st[(c + 4) * 17 + g + 8];
            dst[(size_t)mB * 1024 + idx] = o;
        }
    } else {
        // ---- permB --------------------------------------------------------
        const int bb = bx - 2048;                     // 0..767
        const int w  = bb >> 7;                       // 0..5
        const int gi = (bb & 127) * 256 + threadIdx.x;  // 0..32767
        const int ph = w / 3, w3 = w % 3;
        const float* ws[6] = {Wu, Wr, Wh, Uu, Ur, Uh};
        const float* src = ws[w];
        const int kc   = gi >> 11;
        const int rem  = gi & 2047;
        const int nb   = rem >> 8;
        const int rem2 = rem & 255;
        const int ks   = rem2 >> 7;
        const int wn   = (rem2 >> 5) & 3;
        const int lane = rem2 & 31;
        const int g = lane >> 2, t = lane & 3;
        const int k = kc * 32 + ks * 16 + 2 * t;
        const int n = nb * 64 + wn * 16 + g;
        const float* pk = src + (size_t)k * 512 + n;
        uint4 o;
        o.x = pack2(__ldg(pk),               __ldg(pk + 512));
        o.y = pack2(__ldg(pk + 8 * 512),     __ldg(pk + 9 * 512));
        o.z = pack2(__ldg(pk + 8),           __ldg(pk + 512 + 8));
        o.w = pack2(__ldg(pk + 8 * 512 + 8), __ldg(pk + 9 * 512 + 8));
        const size_t di = ((size_t)((((ph * 16 + kc) * 8 + nb) * 3 + w3) * 2 + ks)) * 128
                        + wn * 32 + lane;
        g_wb[di] = o;
    }
}

// ---- main fused kernel: 2 CTAs/SM (R13 structure) --------------------------
__global__ void __launch_bounds__(TB, 2)
augru_kernel(const float* __restrict__ att, const float* __restrict__ hid,
             const float* __restrict__ b_u, const float* __restrict__ b_r,
             const float* __restrict__ b_h, float* __restrict__ out)
{
    extern __shared__ char smc[];
    const uint32_t sb = smem_u32(smc);
    const int tid  = threadIdx.x;
    const int lane = tid & 31;
    const int wid  = tid >> 5;
    const int g = lane >> 2;
    const int t = lane & 3;
    const int wm  = wid & 3;       // 4 warp-rows of 32
    const int wn2 = wid >> 2;      // 2 warp-cols of 16
    const int m0 = (int)blockIdx.y << 7;
    const int n0 = (int)blockIdx.x << 5;      // 32-col tile
    const int mB0   = m0 >> 4;
    const int nb    = (int)blockIdx.x >> 1;   // 64-col block in permB layout
    const int halfn = (int)blockIdx.x & 1;

    float accU[2][2][4], accR[2][2][4], accX[2][2][4], accS[2][2][4];
    #pragma unroll
    for (int mt = 0; mt < 2; mt++)
        #pragma unroll
        for (int nt = 0; nt < 2; nt++)
            #pragma unroll
            for (int e = 0; e < 4; e++) {
                accU[mt][nt][e] = 0.f; accR[mt][nt][e] = 0.f;
                accX[mt][nt][e] = 0.f; accS[mt][nt][e] = 0.f;
            }

    // chunk = 64 K-columns. 16 chunks (8 per phase).
    auto load_chunk = [&](int c, int b) {
        const int ph = (c >= 8);
        const int cc = c & 7;
        const uint32_t bo = sb + (uint32_t)b * BUF_BYTES;
        // A: 1024 groups, 4 per thread.
        const uint4* Ag = ph ? g_ha : g_xa;
        #pragma unroll
        for (int i = 0; i < 4; i++) {
            const int j   = tid + TB * i;      // 0..1023
            const int mb  = j >> 7;
            const int low = j & 127;
            cp16(bo + j * 16,
                 Ag + ((size_t)(mB0 + mb) * 1024 + cc * 128 + low));
        }
        // B: 768 groups = 2 kc32-blocks x 6 (w,ks) x 64 (our half), 3/thread.
        const uint4* Bsrc = g_wb + ((size_t)((ph * 16 + 2 * cc) * 8 + nb)) * 768
                          + halfn * 64;
        #pragma unroll
        for (int i = 0; i < 3; i++) {
            const int j   = tid + TB * i;      // 0..767
            const int kh  = j / 384;
            const int r2  = j - kh * 384;
            const int sub = r2 >> 6;           // (w,ks) 0..5
            const int low = r2 & 63;
            cp16(bo + A_BYTES + j * 16,
                 Bsrc + (size_t)kh * 6144 + sub * 128 + low);
        }
        cp_commit();
    };

    load_chunk(0, 0);
    load_chunk(1, 1);

    for (int c = 0; c < 16; c++) {
        const int b = c % 3;
        if (c == 15) asm volatile("cp.async.wait_group 0;" ::: "memory");
        else         asm volatile("cp.async.wait_group 1;" ::: "memory");
        __syncthreads();
        if (c + 2 < 16) load_chunk(c + 2, (c + 2) % 3);

        const uint4* Ab4 = reinterpret_cast<const uint4*>(smc + b * BUF_BYTES);
        const uint4* Bb4 = reinterpret_cast<const uint4*>(smc + b * BUF_BYTES + A_BYTES);
        const int ph = (c >= 8);

        #pragma unroll
        for (int ks = 0; ks < 4; ks++) {
            const int khalf = ks >> 1, ks2 = ks & 1;
            uint4 a[2];
            #pragma unroll
            for (int mt = 0; mt < 2; mt++) {
                const int mb = wm * 2 + mt;
                a[mt] = Ab4[mb * 128 + khalf * 64 + ks2 * 32 + lane];
            }
            uint4 bv[3];
            #pragma unroll
            for (int w = 0; w < 3; w++)
                bv[w] = Bb4[khalf * 384 + (w * 2 + ks2) * 64 + wn2 * 32 + lane];
            #pragma unroll
            for (int mt = 0; mt < 2; mt++) {
                mma16(accU[mt][0], a[mt], bv[0].x, bv[0].y);
                mma16(accU[mt][1], a[mt], bv[0].z, bv[0].w);
                mma16(accR[mt][0], a[mt], bv[1].x, bv[1].y);
                mma16(accR[mt][1], a[mt], bv[1].z, bv[1].w);
                if (!ph) {
                    mma16(accX[mt][0], a[mt], bv[2].x, bv[2].y);
                    mma16(accX[mt][1], a[mt], bv[2].z, bv[2].w);
                } else {
                    mma16(accS[mt][0], a[mt], bv[2].x, bv[2].y);
                    mma16(accS[mt][1], a[mt], bv[2].z, bv[2].w);
                }
            }
        }
    }

    // ---- epilogue ----------------------------------------------------------
    #pragma unroll
    for (int mt = 0; mt < 2; mt++) {
        #pragma unroll
        for (int er = 0; er < 2; er++) {
            const int m = m0 + wm * 32 + mt * 16 + g + er * 8;
            const float am = __ldg(att + m);
            const float* hrow = hid + (size_t)m * 512;
            float*       orow = out + (size_t)m * 512;
            #pragma unroll
            for (int nt = 0; nt < 2; nt++) {
                const int col = n0 + wn2 * 16 + nt * 8 + t * 2;
                const float2 h2  = __ldg((const float2*)(hrow + col));
                const float2 bu2 = __ldg((const float2*)(b_u + col));
                const float2 br2 = __ldg((const float2*)(b_r + col));
                const float2 bh2 = __ldg((const float2*)(b_h + col));
                float o[2];
                #pragma unroll
                for (int ec = 0; ec < 2; ec++) {
                    const int e = er * 2 + ec;
                    const float zu = accU[mt][nt][e] + (ec ? bu2.y : bu2.x);
                    const float zr = accR[mt][nt][e] + (ec ? br2.y : br2.x);
                    const float u  = am * sigmoidf_fast(zu);
                    const float r  = sigmoidf_fast(zr);
                    const float hh = tanhf_fast(accX[mt][nt][e] +
                                                r * accS[mt][nt][e] +
                                                (ec ? bh2.y : bh2.x));
                    const float hv = ec ? h2.y : h2.x;
                    o[ec] = (1.0f - u) * hv + u * hh;
                }
                *(float2*)(orow + col) = make_float2(o[0], o[1]);
            }
        }
    }
}

extern "C" void kernel_launch(void* const* d_in, const int* in_sizes, int n_in,
                              void* d_out, int out_size) {
    (void)in_sizes; (void)n_in; (void)out_size;
    const float* x   = (const float*)d_in[0];
    const float* att = (const float*)d_in[1];
    const float* hid = (const float*)d_in[2];
    const float* Wu  = (const float*)d_in[3];
    const float* Uu  = (const float*)d_in[4];
    const float* b_u = (const float*)d_in[5];
    const float* Wr  = (const float*)d_in[6];
    const float* Ur  = (const float*)d_in[7];
    const float* b_r = (const float*)d_in[8];
    const float* Wh  = (const float*)d_in[9];
    const float* Uh  = (const float*)d_in[10];
    const float* b_h = (const float*)d_in[11];
    float* out = (float*)d_out;

    perm_kernel<<<2816, 256>>>(x, hid, Wu, Wr, Wh, Uu, Ur, Uh);

    cudaFuncSetAttribute(augru_kernel,
                         cudaFuncAttributeMaxDynamicSharedMemorySize, SMEM_BYTES);
    dim3 grid(16, 128, 1);   // 16 N-tiles x 128 M-tiles
    augru_kernel<<<grid, TB, SMEM_BYTES>>>(att, hid, b_u, b_r, b_h, out);
}